// round 10
// baseline (speedup 1.0000x reference)
#include <cuda_runtime.h>
#include <cuda_bf16.h>
#include <math.h>
#include <stdint.h>

#define C 64
#define NPIX 16384
#define BATCH 32
#define GCHUNK 16               // gram chunks per batch
#define GK (NPIX / GCHUNK)      // 1024 pixels per gram CTA
#define OTILE 64                // k_out pixels per CTA

// ---------------- scratch (__device__ globals; allocation-free) -------------
__device__ float g_Wg[C * C];                        // gamma*W/sigma
__device__ float g_Mpart[BATCH * GCHUNK * 128 * 64]; // Gram partials (16.8 MB)
__device__ __nv_bfloat16 g_Pb[BATCH * 64 * 128];     // [Ph | Pl] per batch

// ---------------- PTX helpers ----------------------------------------------
__device__ __forceinline__ void ldsm_x4(uint32_t (&r)[4], uint32_t addr) {
    asm volatile("ldmatrix.sync.aligned.m8n8.x4.shared.b16 {%0,%1,%2,%3}, [%4];"
                 : "=r"(r[0]), "=r"(r[1]), "=r"(r[2]), "=r"(r[3]) : "r"(addr));
}
__device__ __forceinline__ void ldsm_x4t(uint32_t (&r)[4], uint32_t addr) {
    asm volatile("ldmatrix.sync.aligned.m8n8.x4.trans.shared.b16 {%0,%1,%2,%3}, [%4];"
                 : "=r"(r[0]), "=r"(r[1]), "=r"(r[2]), "=r"(r[3]) : "r"(addr));
}
__device__ __forceinline__ void mma16816(float (&d)[4], const uint32_t (&a)[4],
                                         uint32_t b0, uint32_t b1) {
    asm volatile(
        "mma.sync.aligned.m16n8k16.row.col.f32.bf16.bf16.f32 "
        "{%0,%1,%2,%3}, {%4,%5,%6,%7}, {%8,%9}, {%0,%1,%2,%3};"
        : "+f"(d[0]), "+f"(d[1]), "+f"(d[2]), "+f"(d[3])
        : "r"(a[0]), "r"(a[1]), "r"(a[2]), "r"(a[3]), "r"(b0), "r"(b1));
}

union BPack { __nv_bfloat162 h2[2]; uint2 u; };

// split one float4 into hi/lo bf16 packs
__device__ __forceinline__ void split4(const float4 v, BPack& hp, BPack& lp) {
    const float f[4] = {v.x, v.y, v.z, v.w};
    __nv_bfloat16 h[4], l[4];
#pragma unroll
    for (int j = 0; j < 4; ++j) {
        h[j] = __float2bfloat16(f[j]);
        l[j] = __float2bfloat16(f[j] - __bfloat162float(h[j]));
    }
    hp.h2[0] = __halves2bfloat162(h[0], h[1]);
    hp.h2[1] = __halves2bfloat162(h[2], h[3]);
    lp.h2[0] = __halves2bfloat162(l[0], l[1]);
    lp.h2[1] = __halves2bfloat162(l[2], l[3]);
}

// ---------------------------------------------------------------------------
// Kernel 1: spectral norm power iteration -> g_Wg = gamma * W / sigma
// ---------------------------------------------------------------------------
__global__ void k_spectral(const float* __restrict__ W,
                           const float* __restrict__ gamma,
                           const float* __restrict__ u) {
    __shared__ float Ws[C][C];
    __shared__ float red[C];
    __shared__ float vs[C];
    const int t = threadIdx.x;  // 64 threads

    for (int r = 0; r < C; ++r) Ws[r][t] = W[r * C + t];
    __syncthreads();

    float tv = 0.f;
    for (int r = 0; r < C; ++r) tv += Ws[r][t] * u[r];
    red[t] = tv * tv;
    __syncthreads();
    if (t == 0) {
        float s = 0.f;
        for (int i = 0; i < C; ++i) s += red[i];
        red[0] = sqrtf(s);
    }
    __syncthreads();
    const float vnorm = fmaxf(red[0], 1e-12f);
    vs[t] = tv / vnorm;
    __syncthreads();

    float wv = 0.f;
    for (int c2 = 0; c2 < C; ++c2) wv += Ws[t][c2] * vs[c2];
    red[t] = wv * wv;
    __syncthreads();
    if (t == 0) {
        float s = 0.f;
        for (int i = 0; i < C; ++i) s += red[i];
        red[0] = sqrtf(s);
    }
    __syncthreads();
    const float nrm = red[0];
    const float sigma = (nrm * nrm) / fmaxf(nrm, 1e-12f);
    const float scale = gamma[0] / sigma;
    for (int c2 = 0; c2 < C; ++c2) g_Wg[t * C + c2] = Ws[t][c2] * scale;
}

// ---------------------------------------------------------------------------
// Kernel 2: Gram partials D = [xh;xl] @ xh^T with register-staged prefetch:
// next tile's LDGs are issued before the MMA phase so global latency overlaps
// tensor work; the barrier sandwich covers only STS.
// grid = (GCHUNK, BATCH), 256 threads (8 warps: 4 m-tiles x 2 n-tiles).
// ---------------------------------------------------------------------------
__global__ void __launch_bounds__(256) k_gram(const float* __restrict__ x) {
    const int chunk = blockIdx.x;
    const int b = blockIdx.y;
    const float* xb = x + (size_t)b * C * NPIX + chunk * GK;

    __shared__ __align__(16) __nv_bfloat16 sa[128][72];  // [hi 0-63 | lo 64-127] x 64 px
    const int tid = threadIdx.x;
    const int lane = tid & 31;
    const int w = tid >> 5;
    const int wm = w & 3;   // m tile: rows 32*wm
    const int wn = w >> 2;  // n tile: cols 32*wn
    const uint32_t sa_base = (uint32_t)__cvta_generic_to_shared(&sa[0][0]);
    const int lch = tid >> 4;   // loader channel 0..63 (4 rows per thread over i)
    const int lcg = tid & 15;   // loader float4 group

    float acc[2][4][4] = {};
    float4 vreg[4];

    // preload tile 0
#pragma unroll
    for (int i = 0; i < 4; ++i)
        vreg[i] = *(const float4*)(xb + (size_t)((tid + 256 * i) >> 4) * NPIX +
                                   4 * ((tid + 256 * i) & 15));
#pragma unroll
    for (int i = 0; i < 4; ++i) {
        const int idx = tid + 256 * i;
        const int ch = idx >> 4, cg = idx & 15;
        BPack hp, lp;
        split4(vreg[i], hp, lp);
        *(uint2*)&sa[ch][4 * cg] = hp.u;
        *(uint2*)&sa[ch + 64][4 * cg] = lp.u;
    }
    __syncthreads();

    for (int t = 0; t < GCHUNK; ++t) {
        // prefetch next tile into registers (overlaps the MMA phase below)
        if (t < GCHUNK - 1) {
            const int p0 = (t + 1) * 64;
#pragma unroll
            for (int i = 0; i < 4; ++i) {
                const int idx = tid + 256 * i;
                vreg[i] = *(const float4*)(xb + (size_t)(idx >> 4) * NPIX + p0 +
                                           4 * (idx & 15));
            }
        }

#pragma unroll
        for (int ks = 0; ks < 4; ++ks) {
            uint32_t a[2][4];
#pragma unroll
            for (int mi = 0; mi < 2; ++mi)
                ldsm_x4(a[mi], sa_base +
                        2u * ((uint32_t)(32 * wm + 16 * mi + (lane & 15)) * 72 +
                              16 * ks + 8 * (lane >> 4)));
#pragma unroll
            for (int nj = 0; nj < 2; ++nj) {
                uint32_t bq[4];  // two n-fragments (ni=2nj, 2nj+1) in one ldsm
                ldsm_x4(bq, sa_base +
                        2u * ((uint32_t)(32 * wn + 16 * nj + 8 * ((lane >> 4) & 1) +
                                         (lane & 7)) * 72 +
                              16 * ks + 8 * ((lane >> 3) & 1)));
#pragma unroll
                for (int mi = 0; mi < 2; ++mi) {
                    mma16816(acc[mi][2 * nj], a[mi], bq[0], bq[1]);
                    mma16816(acc[mi][2 * nj + 1], a[mi], bq[2], bq[3]);
                }
            }
        }
        __syncthreads();

        if (t < GCHUNK - 1) {
#pragma unroll
            for (int i = 0; i < 4; ++i) {
                const int idx = tid + 256 * i;
                const int ch = idx >> 4, cg = idx & 15;
                BPack hp, lp;
                split4(vreg[i], hp, lp);
                *(uint2*)&sa[ch][4 * cg] = hp.u;
                *(uint2*)&sa[ch + 64][4 * cg] = lp.u;
            }
            __syncthreads();
        }
    }

    float* dst = g_Mpart + (size_t)(b * GCHUNK + chunk) * 128 * 64;
#pragma unroll
    for (int mi = 0; mi < 2; ++mi)
#pragma unroll
        for (int ni = 0; ni < 4; ++ni) {
            const int row = 32 * wm + 16 * mi + (lane >> 2);
            const int col = 32 * wn + 8 * ni + 2 * (lane & 3);
            *(float2*)&dst[row * 64 + col] = make_float2(acc[mi][ni][0], acc[mi][ni][1]);
            *(float2*)&dst[(row + 8) * 64 + col] = make_float2(acc[mi][ni][2], acc[mi][ni][3]);
        }
}

// ---------------------------------------------------------------------------
// Kernel 3: reduce partials, M = Dhh + Dlh + Dlh^T; P = M*Wg + I;
// split-store P as bf16 [Ph | Pl] (64 x 128). grid = BATCH.
// ---------------------------------------------------------------------------
__global__ void __launch_bounds__(256) k_P(void) {
    const int b = blockIdx.x;
    __shared__ float Ms[64][65];
    __shared__ float Wgs[64][65];
    const int tid = threadIdx.x;

    for (int i = tid; i < C * C; i += 256)
        Wgs[i >> 6][i & 63] = g_Wg[i];

    for (int i = tid; i < C * C; i += 256) {
        const int c = i >> 6, d = i & 63;
        float s = 0.f;
#pragma unroll
        for (int k = 0; k < GCHUNK; ++k) {
            const float* D = g_Mpart + (size_t)(b * GCHUNK + k) * 128 * 64;
            s += D[c * 64 + d] + D[(64 + c) * 64 + d] + D[(64 + d) * 64 + c];
        }
        Ms[c][d] = s;
    }
    __syncthreads();

    for (int i = tid; i < C * C; i += 256) {
        const int c = i >> 6, e = i & 63;
        float s = (c == e) ? 1.0f : 0.0f;
#pragma unroll
        for (int d = 0; d < C; ++d) s += Ms[c][d] * Wgs[d][e];
        const __nv_bfloat16 hi = __float2bfloat16(s);
        const __nv_bfloat16 lo = __float2bfloat16(s - __bfloat162float(hi));
        g_Pb[((size_t)b * 64 + c) * 128 + e] = hi;
        g_Pb[((size_t)b * 64 + c) * 128 + 64 + e] = lo;
    }
}

// ---------------------------------------------------------------------------
// Kernel 4: out = Ph@xh + Ph@xl + Pl@xh (x4.trans B loads: two n-fragments
// per ldmatrix). (xh,xl) split in-register from fp32 x during tile fill.
// grid = (NPIX/OTILE, BATCH), 256 threads (warps: 4 m-tiles x 2 n-halves).
// ---------------------------------------------------------------------------
__global__ void __launch_bounds__(256) k_out(const float* __restrict__ x,
                                             float* __restrict__ out) {
    const int n0 = blockIdx.x * OTILE;
    const int b = blockIdx.y;
    const float* xb = x + (size_t)b * C * NPIX + n0;

    __shared__ __align__(16) __nv_bfloat16 sb[128][72];   // [xh ch 0-63 | xl ch 64-127]
    __shared__ __align__(16) __nv_bfloat16 sp[64][136];   // [c=64][Ph k 0-63 | Pl 64-127]

    const int tid = threadIdx.x;
    const int lane = tid & 31;
    const int w = tid >> 5;
    const int wm = w & 3;   // m: rows 16*wm
    const int wn = w >> 2;  // n half: cols 32*wn
    const uint32_t sbb = (uint32_t)__cvta_generic_to_shared(&sb[0][0]);
    const uint32_t spb = (uint32_t)__cvta_generic_to_shared(&sp[0][0]);

    // load P tile (64 x 128 bf16) and split-convert x tile (64ch x 64px fp32)
#pragma unroll
    for (int i = 0; i < 4; ++i) {
        const int idx = tid + 256 * i;
        {
            const int row = idx >> 4, g = idx & 15;
            *(uint4*)&sp[row][8 * g] =
                *(const uint4*)&g_Pb[((size_t)b * 64 + row) * 128 + 8 * g];
        }
        {
            const int ch = idx >> 4, cg = idx & 15;
            const float4 v = *(const float4*)(xb + (size_t)ch * NPIX + 4 * cg);
            BPack hp, lp;
            split4(v, hp, lp);
            *(uint2*)&sb[ch][4 * cg] = hp.u;
            *(uint2*)&sb[ch + 64][4 * cg] = lp.u;
        }
    }
    __syncthreads();

    float acc[4][4] = {};
#pragma unroll
    for (int kk = 0; kk < 4; ++kk) {
        uint32_t aph[4], apl[4];
        ldsm_x4(aph, spb + 2u * ((uint32_t)(16 * wm + (lane & 15)) * 136 +
                                 16 * kk + 8 * (lane >> 4)));
        ldsm_x4(apl, spb + 2u * ((uint32_t)(16 * wm + (lane & 15)) * 136 +
                                 64 + 16 * kk + 8 * (lane >> 4)));
#pragma unroll
        for (int nj = 0; nj < 2; ++nj) {
            const uint32_t cb = 32 * wn + 16 * nj + 8 * ((lane >> 4) & 1);
            uint32_t bh[4], bl[4];  // k16 x n16: {ni=2nj: r0,r1} {ni=2nj+1: r2,r3}
            ldsm_x4t(bh, sbb + 2u * ((uint32_t)(16 * kk + 8 * ((lane >> 3) & 1) +
                                               (lane & 7)) * 72 + cb));
            ldsm_x4t(bl, sbb + 2u * ((uint32_t)(64 + 16 * kk + 8 * ((lane >> 3) & 1) +
                                               (lane & 7)) * 72 + cb));
            mma16816(acc[2 * nj], aph, bh[0], bh[1]);       // Ph @ xh
            mma16816(acc[2 * nj], aph, bl[0], bl[1]);       // Ph @ xl
            mma16816(acc[2 * nj], apl, bh[0], bh[1]);       // Pl @ xh
            mma16816(acc[2 * nj + 1], aph, bh[2], bh[3]);
            mma16816(acc[2 * nj + 1], aph, bl[2], bl[3]);
            mma16816(acc[2 * nj + 1], apl, bh[2], bh[3]);
        }
    }

    float* ob = out + (size_t)b * C * NPIX + n0;
#pragma unroll
    for (int ni = 0; ni < 4; ++ni) {
        const int row = 16 * wm + (lane >> 2);
        const int col = 32 * wn + 8 * ni + 2 * (lane & 3);
        *(float2*)&ob[(size_t)row * NPIX + col] = make_float2(acc[ni][0], acc[ni][1]);
        *(float2*)&ob[(size_t)(row + 8) * NPIX + col] = make_float2(acc[ni][2], acc[ni][3]);
    }
}

// ---------------------------------------------------------------------------
extern "C" void kernel_launch(void* const* d_in, const int* in_sizes, int n_in,
                              void* d_out, int out_size) {
    const float* x = (const float*)d_in[0];
    const float* W = (const float*)d_in[1];
    const float* gamma = (const float*)d_in[2];
    const float* u = (const float*)d_in[3];
    float* out = (float*)d_out;

    k_spectral<<<1, 64>>>(W, gamma, u);

    dim3 gg(GCHUNK, BATCH);
    k_gram<<<gg, 256>>>(x);

    k_P<<<BATCH, 256>>>();

    dim3 go(NPIX / OTILE, BATCH);
    k_out<<<go, 256>>>(x, out);
}